// round 16
// baseline (speedup 1.0000x reference)
#include <cuda_runtime.h>
#include <cstdint>

#define BATCH 16384
#define F 512
#define CSZ 16            // cluster size (CTAs), one per 32 output columns
#define NC (F/CSZ)        // 32 columns per CTA
#define NTHR 512          // 16 warps: g = w>>3 (0=z,1=h), kw = w&7, lane = column

// ---------------- scratch for precomputed input projections ----------------
__device__ float g_Xz[(size_t)BATCH * F];   // x@Wz + bz
__device__ float g_Xh[(size_t)BATCH * F];   // x@Wh + bh

// ============================ GEMM (batch-parallel part) ====================
#define GBM 128
#define GBN 64
#define GBK 16

__global__ void __launch_bounds__(256) gemm_kernel(
    const float* __restrict__ A,
    const float* __restrict__ Wz, const float* __restrict__ bz,
    const float* __restrict__ Wh, const float* __restrict__ bh)
{
    const float* W    = blockIdx.z ? Wh : Wz;
    const float* bias = blockIdx.z ? bh : bz;
    float* out        = blockIdx.z ? g_Xh : g_Xz;

    __shared__ float As[GBK][GBM];
    __shared__ float Bs[GBK][GBN];

    const int tid  = threadIdx.x;
    const int row0 = blockIdx.y * GBM;
    const int col0 = blockIdx.x * GBN;
    const int ty = tid >> 4;
    const int tx = tid & 15;
    const int ar = tid >> 1;
    const int aseg = (tid & 1) * 8;

    float acc[8][4];
#pragma unroll
    for (int i = 0; i < 8; i++)
#pragma unroll
        for (int j = 0; j < 4; j++) acc[i][j] = 0.f;

    for (int k0 = 0; k0 < F; k0 += GBK) {
        float4 av0 = *(const float4*)(A + (size_t)(row0 + ar) * F + k0 + aseg);
        float4 av1 = *(const float4*)(A + (size_t)(row0 + ar) * F + k0 + aseg + 4);
        float4 bv  = *(const float4*)(W + (size_t)(k0 + ty) * F + col0 + tx * 4);
        As[aseg+0][ar] = av0.x; As[aseg+1][ar] = av0.y;
        As[aseg+2][ar] = av0.z; As[aseg+3][ar] = av0.w;
        As[aseg+4][ar] = av1.x; As[aseg+5][ar] = av1.y;
        As[aseg+6][ar] = av1.z; As[aseg+7][ar] = av1.w;
        *(float4*)&Bs[ty][tx * 4] = bv;
        __syncthreads();
#pragma unroll
        for (int k = 0; k < GBK; k++) {
            float4 a0 = *(const float4*)&As[k][ty * 8];
            float4 a1 = *(const float4*)&As[k][ty * 8 + 4];
            float4 b  = *(const float4*)&Bs[k][tx * 4];
            float av[8] = {a0.x, a0.y, a0.z, a0.w, a1.x, a1.y, a1.z, a1.w};
            float bb[4] = {b.x, b.y, b.z, b.w};
#pragma unroll
            for (int i = 0; i < 8; i++)
#pragma unroll
                for (int j = 0; j < 4; j++) acc[i][j] += av[i] * bb[j];
        }
        __syncthreads();
    }

#pragma unroll
    for (int i = 0; i < 8; i++) {
        const int r = row0 + ty * 8 + i;
        float4 v;
        v.x = acc[i][0] + bias[col0 + tx * 4 + 0];
        v.y = acc[i][1] + bias[col0 + tx * 4 + 1];
        v.z = acc[i][2] + bias[col0 + tx * 4 + 2];
        v.w = acc[i][3] + bias[col0 + tx * 4 + 3];
        *(float4*)(out + (size_t)r * F + col0 + tx * 4) = v;
    }
}

// ======================= sequential recurrence (cluster) ====================

__device__ __forceinline__ unsigned smem_u32(const void* p) {
    return (unsigned)__cvta_generic_to_shared(p);
}

__global__ void __launch_bounds__(NTHR, 1) memrnn_kernel(
    const float* __restrict__ Uz, const float* __restrict__ Uh,
    float* __restrict__ out)
{
    __shared__ __align__(16) float mbuf[2][F];     // ping-pong full m vector
    __shared__ __align__(16) float part[16][NC];   // [g*8+kw][col] partial dots
    __shared__ __align__(16) float mstage[NC];     // staging for DSMEM push
    __shared__ __align__(16) unsigned flags[CSZ];  // monotonic step flags, 1/source

    const int tid = threadIdx.x;
    const int w   = tid >> 5;     // warp 0..15
    const int l   = tid & 31;     // lane = local column
    const int g   = w >> 3;       // 0 = z-gate, 1 = h-gate
    const int kw  = w & 7;        // k-slice: m elements [kw*64, kw*64+64)
    unsigned rank;
    asm("mov.u32 %0, %%cluster_ctarank;" : "=r"(rank));
    const int c = (int)rank;
    const int gcol = c * NC + l;  // this thread's global output column

    // ---- U slice in registers: rows [kw*64, kw*64+64) of column gcol -------
    const float* Usrc = (g ? Uh : Uz) + gcol;
    unsigned long long u[32];
#pragma unroll
    for (int i = 0; i < 32; i++) {
        float a0 = Usrc[(size_t)(kw * 64 + 2 * i)     * F];
        float a1 = Usrc[(size_t)(kw * 64 + 2 * i + 1) * F];
        asm("mov.b64 %0, {%1, %2};" : "=l"(u[i]) : "f"(a0), "f"(a1));
    }

    // m_0 = 0; flags = 0
    if (tid < F) mbuf[0][tid] = 0.f;
    if (tid < CSZ) flags[tid] = 0u;

    __syncthreads();
    asm volatile("barrier.cluster.arrive.aligned;" ::: "memory");
    asm volatile("barrier.cluster.wait.aligned;"   ::: "memory");

    // ---- X register ring (warp 0 only; lane l = column l), depth 2 ----
    float xz[2], xh[2], m_old = 0.f;
    if (w == 0) {
        xz[0] = g_Xz[gcol];              xh[0] = g_Xh[gcol];
        xz[1] = g_Xz[(size_t)F + gcol];  xh[1] = g_Xh[(size_t)F + gcol];
    }

    for (int t = 0; t < BATCH; t++) {
        const int rb   = t & 1;
        const int wbuf = rb ^ 1;

        // ---- dot: all lanes of a warp read the SAME m address (broadcast) ----
        const float* mp = mbuf[rb] + kw * 64;
        unsigned long long a0 = 0ull, a1 = 0ull, a2 = 0ull, a3 = 0ull;
#pragma unroll
        for (int i = 0; i < 8; i++) {
            ulonglong2 mv0 = *(const ulonglong2*)(mp + i * 8);
            ulonglong2 mv1 = *(const ulonglong2*)(mp + i * 8 + 4);
            asm("fma.rn.f32x2 %0, %1, %2, %0;" : "+l"(a0) : "l"(mv0.x), "l"(u[4 * i]));
            asm("fma.rn.f32x2 %0, %1, %2, %0;" : "+l"(a1) : "l"(mv0.y), "l"(u[4 * i + 1]));
            asm("fma.rn.f32x2 %0, %1, %2, %0;" : "+l"(a2) : "l"(mv1.x), "l"(u[4 * i + 2]));
            asm("fma.rn.f32x2 %0, %1, %2, %0;" : "+l"(a3) : "l"(mv1.y), "l"(u[4 * i + 3]));
        }
        float s0, s1, s2, s3, s4, s5, s6, s7;
        asm("mov.b64 {%0, %1}, %2;" : "=f"(s0), "=f"(s1) : "l"(a0));
        asm("mov.b64 {%0, %1}, %2;" : "=f"(s2), "=f"(s3) : "l"(a1));
        asm("mov.b64 {%0, %1}, %2;" : "=f"(s4), "=f"(s5) : "l"(a2));
        asm("mov.b64 {%0, %1}, %2;" : "=f"(s6), "=f"(s7) : "l"(a3));
        float ps = ((s0 + s1) + (s2 + s3)) + ((s4 + s5) + (s6 + s7));

        part[w][l] = ps;      // lane -> bank, conflict-free
        __syncthreads();      // sync #1: partials visible to warp 0

        // ---- warp 0: reduce + gates + DSMEM push + flag publish + poll ----
        if (w == 0) {
            float zs = ps         + part[1][l]  + part[2][l]  + part[3][l]
                     + part[4][l] + part[5][l]  + part[6][l]  + part[7][l]
                     + xz[rb];
            float hs = part[8][l]  + part[9][l]  + part[10][l] + part[11][l]
                     + part[12][l] + part[13][l] + part[14][l] + part[15][l]
                     + xh[rb];
            float ez = __expf(-zs);
            float z  = __fdividef(1.0f, 1.0f + ez);
            float e2 = __expf(-2.0f * hs);
            float h  = __fdividef(2.0f, 1.0f + e2) - 1.0f;    // tanh
            float mn = fmaf(z, h - m_old, m_old);
            m_old = mn;

            if (t + 1 < BATCH) {
                mstage[l] = mn;
                __syncwarp();
                // lane l (l<16) pushes the FULL 128B chunk to rank l's
                // mbuf[wbuf][c*NC..], then release-publishes flags[c] = t+1
                // at rank l. 16 distinct flag words per receiver -> no
                // single-address serialization (the R15 mbarrier killer).
                if (l < 16) {
                    unsigned ldst  = smem_u32(&mbuf[wbuf][c * NC]);
                    unsigned lflag = smem_u32(&flags[c]);
                    unsigned rdst, rflag;
                    asm("mapa.shared::cluster.u32 %0, %1, %2;" : "=r"(rdst)  : "r"(ldst),  "r"(l));
                    asm("mapa.shared::cluster.u32 %0, %1, %2;" : "=r"(rflag) : "r"(lflag), "r"(l));
                    const float4* sp4 = (const float4*)&mstage[0];
#pragma unroll
                    for (int i = 0; i < 8; i++) {
                        float4 v = sp4[i];
                        asm volatile("st.shared::cluster.v4.f32 [%0], {%1,%2,%3,%4};"
                                     :: "r"(rdst + i * 16),
                                        "f"(v.x), "f"(v.y), "f"(v.z), "f"(v.w) : "memory");
                    }
                    // release store: orders this thread's prior remote stores
                    // before the flag value becomes visible at cluster scope.
                    asm volatile("st.release.cluster.shared::cluster.u32 [%0], %1;"
                                 :: "r"(rflag), "r"(t + 1u) : "memory");
                }

                out[(size_t)t * F + gcol] = mn;      // fire-and-forget

                if (t + 2 < BATCH) {                 // refill X ring for t+2
                    xz[rb] = g_Xz[(size_t)(t + 2) * F + gcol];
                    xh[rb] = g_Xh[(size_t)(t + 2) * F + gcol];
                }

                // ---- poll: lane l (l<16) waits for flags[l] >= t+1 ----
                if (l < 16) {
                    unsigned fa = smem_u32(&flags[l]);
                    unsigned v;
                    do {
                        asm volatile("ld.relaxed.cluster.shared::cta.u32 %0, [%1];"
                                     : "=r"(v) : "r"(fa) : "memory");
                    } while (__any_sync(0x0000FFFFu, v < (unsigned)(t + 1)));
                    // acquire re-read: synchronizes-with the sender's release
                    // store, making the pushed chunk visible to this thread
                    // (and to the whole CTA via the barrier below).
                    asm volatile("ld.acquire.cluster.shared::cta.u32 %0, [%1];"
                                 : "=r"(v) : "r"(fa) : "memory");
                }
            } else {
                out[(size_t)t * F + gcol] = mn;
            }
        }

        // ---- sync #2: all warps wait for warp 0's poll; acquires + CTA
        //      barrier give every thread visibility of the new mbuf[wbuf].
        if (t + 1 < BATCH) {
            __syncthreads();
        }
    }

    asm volatile("barrier.cluster.arrive.aligned;" ::: "memory");
    asm volatile("barrier.cluster.wait.aligned;"   ::: "memory");
}

// ================================ launch ====================================
extern "C" void kernel_launch(void* const* d_in, const int* in_sizes, int n_in,
                              void* d_out, int out_size)
{
    const float* x  = (const float*)d_in[0];
    const float* Wz = (const float*)d_in[1];
    const float* Uz = (const float*)d_in[2];
    const float* bz = (const float*)d_in[3];
    const float* Wh = (const float*)d_in[4];
    const float* Uh = (const float*)d_in[5];
    const float* bh = (const float*)d_in[6];
    float* out = (float*)d_out;

    dim3 ggrid(F / GBN, BATCH / GBM, 2);
    gemm_kernel<<<ggrid, 256>>>(x, Wz, bz, Wh, bh);

    cudaFuncSetAttribute((const void*)memrnn_kernel,
                         cudaFuncAttributeNonPortableClusterSizeAllowed, 1);

    cudaLaunchConfig_t cfg = {};
    cfg.gridDim  = dim3(CSZ, 1, 1);
    cfg.blockDim = dim3(NTHR, 1, 1);
    cfg.dynamicSmemBytes = 0;
    cfg.stream = 0;
    cudaLaunchAttribute attrs[1];
    attrs[0].id = cudaLaunchAttributeClusterDimension;
    attrs[0].val.clusterDim.x = CSZ;
    attrs[0].val.clusterDim.y = 1;
    attrs[0].val.clusterDim.z = 1;
    cfg.attrs = attrs;
    cfg.numAttrs = 1;

    cudaLaunchKernelEx(&cfg, memrnn_kernel, Uz, Uh, out);
}

// round 17
// speedup vs baseline: 1.2286x; 1.2286x over previous
#include <cuda_runtime.h>
#include <cstdint>

#define BATCH 16384
#define F 512
#define CSZ 16            // cluster size (CTAs), one per 32 output columns
#define NC (F/CSZ)        // 32 columns per CTA
#define NTHR 512          // 16 warps: g = w>>3 (0=z,1=h), kw = w&7, lane = column

// ---------------- scratch for precomputed input projections ----------------
__device__ float g_Xz[(size_t)BATCH * F];   // x@Wz + bz
__device__ float g_Xh[(size_t)BATCH * F];   // x@Wh + bh

// ============================ GEMM (batch-parallel part) ====================
#define GBM 128
#define GBN 64
#define GBK 16

__global__ void __launch_bounds__(256) gemm_kernel(
    const float* __restrict__ A,
    const float* __restrict__ Wz, const float* __restrict__ bz,
    const float* __restrict__ Wh, const float* __restrict__ bh)
{
    const float* W    = blockIdx.z ? Wh : Wz;
    const float* bias = blockIdx.z ? bh : bz;
    float* out        = blockIdx.z ? g_Xh : g_Xz;

    __shared__ float As[GBK][GBM];
    __shared__ float Bs[GBK][GBN];

    const int tid  = threadIdx.x;
    const int row0 = blockIdx.y * GBM;
    const int col0 = blockIdx.x * GBN;
    const int ty = tid >> 4;
    const int tx = tid & 15;
    const int ar = tid >> 1;
    const int aseg = (tid & 1) * 8;

    float acc[8][4];
#pragma unroll
    for (int i = 0; i < 8; i++)
#pragma unroll
        for (int j = 0; j < 4; j++) acc[i][j] = 0.f;

    for (int k0 = 0; k0 < F; k0 += GBK) {
        float4 av0 = *(const float4*)(A + (size_t)(row0 + ar) * F + k0 + aseg);
        float4 av1 = *(const float4*)(A + (size_t)(row0 + ar) * F + k0 + aseg + 4);
        float4 bv  = *(const float4*)(W + (size_t)(k0 + ty) * F + col0 + tx * 4);
        As[aseg+0][ar] = av0.x; As[aseg+1][ar] = av0.y;
        As[aseg+2][ar] = av0.z; As[aseg+3][ar] = av0.w;
        As[aseg+4][ar] = av1.x; As[aseg+5][ar] = av1.y;
        As[aseg+6][ar] = av1.z; As[aseg+7][ar] = av1.w;
        *(float4*)&Bs[ty][tx * 4] = bv;
        __syncthreads();
#pragma unroll
        for (int k = 0; k < GBK; k++) {
            float4 a0 = *(const float4*)&As[k][ty * 8];
            float4 a1 = *(const float4*)&As[k][ty * 8 + 4];
            float4 b  = *(const float4*)&Bs[k][tx * 4];
            float av[8] = {a0.x, a0.y, a0.z, a0.w, a1.x, a1.y, a1.z, a1.w};
            float bb[4] = {b.x, b.y, b.z, b.w};
#pragma unroll
            for (int i = 0; i < 8; i++)
#pragma unroll
                for (int j = 0; j < 4; j++) acc[i][j] += av[i] * bb[j];
        }
        __syncthreads();
    }

#pragma unroll
    for (int i = 0; i < 8; i++) {
        const int r = row0 + ty * 8 + i;
        float4 v;
        v.x = acc[i][0] + bias[col0 + tx * 4 + 0];
        v.y = acc[i][1] + bias[col0 + tx * 4 + 1];
        v.z = acc[i][2] + bias[col0 + tx * 4 + 2];
        v.w = acc[i][3] + bias[col0 + tx * 4 + 3];
        *(float4*)(out + (size_t)r * F + col0 + tx * 4) = v;
    }
}

// ======================= sequential recurrence (cluster) ====================

__device__ __forceinline__ unsigned smem_u32(const void* p) {
    return (unsigned)__cvta_generic_to_shared(p);
}

__global__ void __launch_bounds__(NTHR, 1) memrnn_kernel(
    const float* __restrict__ Uz, const float* __restrict__ Uh,
    float* __restrict__ out)
{
    __shared__ __align__(16) float mbuf[2][F];       // ping-pong full m vector
    __shared__ __align__(16) float part[2][16][NC];  // double-buffered partials
    __shared__ __align__(16) float mstage[NC];       // staging for DSMEM push
    __shared__ __align__(16) unsigned flags[CSZ];    // monotonic step flag per source

    const int tid = threadIdx.x;
    const int w   = tid >> 5;     // warp 0..15
    const int l   = tid & 31;     // lane = local column
    const int g   = w >> 3;       // 0 = z-gate, 1 = h-gate
    const int kw  = w & 7;        // k-slice: m elements [kw*64, kw*64+64)
    unsigned rank;
    asm("mov.u32 %0, %%cluster_ctarank;" : "=r"(rank));
    const int c = (int)rank;
    const int gcol = c * NC + l;  // this thread's global output column

    // ---- U slice in registers: rows [kw*64, kw*64+64) of column gcol -------
    const float* Usrc = (g ? Uh : Uz) + gcol;
    unsigned long long u[32];
#pragma unroll
    for (int i = 0; i < 32; i++) {
        float a0 = Usrc[(size_t)(kw * 64 + 2 * i)     * F];
        float a1 = Usrc[(size_t)(kw * 64 + 2 * i + 1) * F];
        asm("mov.b64 %0, {%1, %2};" : "=l"(u[i]) : "f"(a0), "f"(a1));
    }

    // m_0 = 0; flags = 0
    if (tid < F) mbuf[0][tid] = 0.f;
    if (tid < CSZ) flags[tid] = 0u;

    __syncthreads();
    asm volatile("barrier.cluster.arrive.aligned;" ::: "memory");
    asm volatile("barrier.cluster.wait.aligned;"   ::: "memory");

    // ---- X register ring (warp 0 only; lane l = column l), depth 2 ----
    float xz[2], xh[2], m_old = 0.f;
    if (w == 0) {
        xz[0] = g_Xz[gcol];              xh[0] = g_Xh[gcol];
        xz[1] = g_Xz[(size_t)F + gcol];  xh[1] = g_Xh[(size_t)F + gcol];
    }

    for (int t = 0; t < BATCH; t++) {
        const int pb = t & 1;

        // ---- per-warp wait: this warp's dot needs ONLY source chunks
        //      2kw and 2kw+1 of m_t. Tail = max of 2 senders, not 16.
        if (t > 0) {
            if (l < 2) {
                unsigned fa = smem_u32(&flags[2 * kw + l]);
                unsigned v;
                do {
                    asm volatile("ld.relaxed.cluster.shared::cta.u32 %0, [%1];"
                                 : "=r"(v) : "r"(fa) : "memory");
                } while (v < (unsigned)t);
                // acquire: synchronizes-with the sender's release store,
                // making the pushed chunk visible; __syncwarp below extends
                // that visibility to the whole warp.
                asm volatile("ld.acquire.cluster.shared::cta.u32 %0, [%1];"
                             : "=r"(v) : "r"(fa) : "memory");
            }
            __syncwarp();
        }

        // ---- dot: all lanes of a warp read the SAME m address (broadcast) ----
        const float* mp = mbuf[pb] + kw * 64;
        unsigned long long a0 = 0ull, a1 = 0ull, a2 = 0ull, a3 = 0ull;
#pragma unroll
        for (int i = 0; i < 8; i++) {
            ulonglong2 mv0 = *(const ulonglong2*)(mp + i * 8);
            ulonglong2 mv1 = *(const ulonglong2*)(mp + i * 8 + 4);
            asm("fma.rn.f32x2 %0, %1, %2, %0;" : "+l"(a0) : "l"(mv0.x), "l"(u[4 * i]));
            asm("fma.rn.f32x2 %0, %1, %2, %0;" : "+l"(a1) : "l"(mv0.y), "l"(u[4 * i + 1]));
            asm("fma.rn.f32x2 %0, %1, %2, %0;" : "+l"(a2) : "l"(mv1.x), "l"(u[4 * i + 2]));
            asm("fma.rn.f32x2 %0, %1, %2, %0;" : "+l"(a3) : "l"(mv1.y), "l"(u[4 * i + 3]));
        }
        float s0, s1, s2, s3, s4, s5, s6, s7;
        asm("mov.b64 {%0, %1}, %2;" : "=f"(s0), "=f"(s1) : "l"(a0));
        asm("mov.b64 {%0, %1}, %2;" : "=f"(s2), "=f"(s3) : "l"(a1));
        asm("mov.b64 {%0, %1}, %2;" : "=f"(s4), "=f"(s5) : "l"(a2));
        asm("mov.b64 {%0, %1}, %2;" : "=f"(s6), "=f"(s7) : "l"(a3));
        float ps = ((s0 + s1) + (s2 + s3)) + ((s4 + s5) + (s6 + s7));

        part[pb][w][l] = ps;  // lane -> bank, conflict-free; double-buffered
        __syncthreads();      // sync1: partials visible to warp 0

        // ---- warp 0: reduce + gates + DSMEM push + output ----
        // (other warps run ahead to their next per-warp wait / dot)
        if (w == 0) {
            float zs = ps             + part[pb][1][l]  + part[pb][2][l]  + part[pb][3][l]
                     + part[pb][4][l] + part[pb][5][l]  + part[pb][6][l]  + part[pb][7][l]
                     + xz[pb];
            float hs = part[pb][8][l]  + part[pb][9][l]  + part[pb][10][l] + part[pb][11][l]
                     + part[pb][12][l] + part[pb][13][l] + part[pb][14][l] + part[pb][15][l]
                     + xh[pb];
            float ez = __expf(-zs);
            float z  = __fdividef(1.0f, 1.0f + ez);
            float e2 = __expf(-2.0f * hs);
            float h  = __fdividef(2.0f, 1.0f + e2) - 1.0f;    // tanh
            float mn = fmaf(z, h - m_old, m_old);
            m_old = mn;

            if (t + 1 < BATCH) {
                mstage[l] = mn;
                __syncwarp();
                // lane l (l<16) pushes the full 128B chunk to rank l's
                // mbuf[(t+1)&1][c*NC..], then release-publishes flags[c]=t+1.
                if (l < 16) {
                    unsigned ldst  = smem_u32(&mbuf[pb ^ 1][c * NC]);
                    unsigned lflag = smem_u32(&flags[c]);
                    unsigned rdst, rflag;
                    asm("mapa.shared::cluster.u32 %0, %1, %2;" : "=r"(rdst)  : "r"(ldst),  "r"(l));
                    asm("mapa.shared::cluster.u32 %0, %1, %2;" : "=r"(rflag) : "r"(lflag), "r"(l));
                    const float4* sp4 = (const float4*)&mstage[0];
#pragma unroll
                    for (int i = 0; i < 8; i++) {
                        float4 v = sp4[i];
                        asm volatile("st.shared::cluster.v4.f32 [%0], {%1,%2,%3,%4};"
                                     :: "r"(rdst + i * 16),
                                        "f"(v.x), "f"(v.y), "f"(v.z), "f"(v.w) : "memory");
                    }
                    asm volatile("st.release.cluster.shared::cluster.u32 [%0], %1;"
                                 :: "r"(rflag), "r"(t + 1u) : "memory");
                }
            }

            out[(size_t)t * F + gcol] = mn;          // fire-and-forget

            if (t + 2 < BATCH) {                     // refill X ring for t+2
                xz[pb] = g_Xz[(size_t)(t + 2) * F + gcol];
                xh[pb] = g_Xh[(size_t)(t + 2) * F + gcol];
            }
        }
        // NO global wait here: each warp's next iteration waits only its own
        // two source flags. Buffer-reuse safety (depth-2 mbuf) is guaranteed
        // by: send(t+1) <= sync1(t+1) <= all-flags(t+1) <= every source's
        // sync1(t) <= every warp everywhere finished reading mbuf[t&1].
    }

    asm volatile("barrier.cluster.arrive.aligned;" ::: "memory");
    asm volatile("barrier.cluster.wait.aligned;"   ::: "memory");
}

// ================================ launch ====================================
extern "C" void kernel_launch(void* const* d_in, const int* in_sizes, int n_in,
                              void* d_out, int out_size)
{
    const float* x  = (const float*)d_in[0];
    const float* Wz = (const float*)d_in[1];
    const float* Uz = (const float*)d_in[2];
    const float* bz = (const float*)d_in[3];
    const float* Wh = (const float*)d_in[4];
    const float* Uh = (const float*)d_in[5];
    const float* bh = (const float*)d_in[6];
    float* out = (float*)d_out;

    dim3 ggrid(F / GBN, BATCH / GBM, 2);
    gemm_kernel<<<ggrid, 256>>>(x, Wz, bz, Wh, bh);

    cudaFuncSetAttribute((const void*)memrnn_kernel,
                         cudaFuncAttributeNonPortableClusterSizeAllowed, 1);

    cudaLaunchConfig_t cfg = {};
    cfg.gridDim  = dim3(CSZ, 1, 1);
    cfg.blockDim = dim3(NTHR, 1, 1);
    cfg.dynamicSmemBytes = 0;
    cfg.stream = 0;
    cudaLaunchAttribute attrs[1];
    attrs[0].id = cudaLaunchAttributeClusterDimension;
    attrs[0].val.clusterDim.x = CSZ;
    attrs[0].val.clusterDim.y = 1;
    attrs[0].val.clusterDim.z = 1;
    cfg.attrs = attrs;
    cfg.numAttrs = 1;

    cudaLaunchKernelEx(&cfg, memrnn_kernel, Uz, Uh, out);
}